// round 6
// baseline (speedup 1.0000x reference)
#include <cuda_runtime.h>
#include <cuda_bf16.h>

#define DM 2048
#define NB 32
#define NT 8
#define NH 32
#define DH 64
#define CT 1016
#define SEQ 1024
#define MROWS 256   // NB*NT

// ---------------- scratch (device globals; no allocation allowed) ----------------
__device__ float g_q   [NB*NH*NT*DH];   // [b][h][t][d]
__device__ float g_kn  [NB*NH*NT*DH];
__device__ float g_vn  [NB*NH*NT*DH];

// bf16 hi/lo split scratch
__device__ __align__(16) __nv_bfloat16 g_wqh[DM*DM], g_wql[DM*DM];
__device__ __align__(16) __nv_bfloat16 g_wkh[DM*DM], g_wkl[DM*DM];
__device__ __align__(16) __nv_bfloat16 g_wvh[DM*DM], g_wvl[DM*DM];
__device__ __align__(16) __nv_bfloat16 g_woh[DM*DM], g_wol[DM*DM];
__device__ __align__(16) __nv_bfloat16 g_xh[MROWS*DM], g_xl[MROWS*DM];
__device__ __align__(16) __nv_bfloat16 g_ah[MROWS*DM], g_al[MROWS*DM];  // attn out split

// ---------------- cp.async helpers ----------------
__device__ __forceinline__ void cp16(unsigned dst, const void* src) {
    asm volatile("cp.async.cg.shared.global [%0], [%1], 16;\n" :: "r"(dst), "l"(src));
}
__device__ __forceinline__ void cp8(unsigned dst, const void* src) {
    asm volatile("cp.async.ca.shared.global [%0], [%1], 8;\n" :: "r"(dst), "l"(src));
}
__device__ __forceinline__ void cp_commit() {
    asm volatile("cp.async.commit_group;\n");
}
__device__ __forceinline__ void cp_wait1() {
    asm volatile("cp.async.wait_group 1;\n");
}
__device__ __forceinline__ void cp_wait0() {
    asm volatile("cp.async.wait_group 0;\n");
}

// ---------------- f32x2 packed math ----------------
__device__ __forceinline__ void ffma2(unsigned long long& acc, unsigned long long a,
                                      unsigned long long b) {
    asm("fma.rn.f32x2 %0, %1, %2, %0;" : "+l"(acc) : "l"(a), "l"(b));
}
__device__ __forceinline__ void unpack2(unsigned long long a, float& lo, float& hi) {
    asm("mov.b64 {%0,%1}, %2;" : "=f"(lo), "=f"(hi) : "l"(a));
}
__device__ __forceinline__ unsigned long long pack_dup(float v) {
    unsigned long long r;
    asm("mov.b64 %0, {%1,%1};" : "=l"(r) : "f"(v));
    return r;
}
__device__ __forceinline__ unsigned long long pack2(float x, float y) {
    unsigned long long r;
    asm("mov.b64 %0, {%1,%2};" : "=l"(r) : "f"(x), "f"(y));
    return r;
}

// ---------------- mma / ldmatrix helpers ----------------
__device__ __forceinline__ void ldm_x4(unsigned addr, unsigned& r0, unsigned& r1,
                                       unsigned& r2, unsigned& r3) {
    asm volatile("ldmatrix.sync.aligned.m8n8.x4.shared.b16 {%0,%1,%2,%3}, [%4];"
                 : "=r"(r0), "=r"(r1), "=r"(r2), "=r"(r3) : "r"(addr));
}
__device__ __forceinline__ void mma16(float* c, const unsigned* a, unsigned b0, unsigned b1) {
    asm volatile(
        "mma.sync.aligned.m16n8k16.row.col.f32.bf16.bf16.f32 "
        "{%0,%1,%2,%3}, {%4,%5,%6,%7}, {%8,%9}, {%0,%1,%2,%3};"
        : "+f"(c[0]), "+f"(c[1]), "+f"(c[2]), "+f"(c[3])
        : "r"(a[0]), "r"(a[1]), "r"(a[2]), "r"(a[3]), "r"(b0), "r"(b1));
}

// =================================================================================
// Prepass: split fp32 -> bf16 hi/lo for 4 weights + x, batch-2 for MLP
// =================================================================================
__device__ __forceinline__ void split8_store(const float4 f0, const float4 f1,
                                             __nv_bfloat16* dh, __nv_bfloat16* dl, size_t off) {
    float a[8] = {f0.x, f0.y, f0.z, f0.w, f1.x, f1.y, f1.z, f1.w};
    unsigned short h[8], l[8];
#pragma unroll
    for (int i = 0; i < 8; i++) {
        __nv_bfloat16 hb = __float2bfloat16(a[i]);
        __nv_bfloat16 lb = __float2bfloat16(a[i] - __bfloat162float(hb));
        h[i] = __bfloat16_as_ushort(hb);
        l[i] = __bfloat16_as_ushort(lb);
    }
    uint4 hs, ls;
    hs.x = (unsigned)h[0] | ((unsigned)h[1] << 16);
    hs.y = (unsigned)h[2] | ((unsigned)h[3] << 16);
    hs.z = (unsigned)h[4] | ((unsigned)h[5] << 16);
    hs.w = (unsigned)h[6] | ((unsigned)h[7] << 16);
    ls.x = (unsigned)l[0] | ((unsigned)l[1] << 16);
    ls.y = (unsigned)l[2] | ((unsigned)l[3] << 16);
    ls.z = (unsigned)l[4] | ((unsigned)l[5] << 16);
    ls.w = (unsigned)l[6] | ((unsigned)l[7] << 16);
    ((uint4*)dh)[off] = hs;
    ((uint4*)dl)[off] = ls;
}

#define W8 (DM * DM / 8)
#define X8 (MROWS * DM / 8)

__device__ __forceinline__ void conv_route(int id, const float* wq, const float* wk,
                                           const float* wv, const float* wo, const float* x,
                                           const float*& src, __nv_bfloat16*& dh,
                                           __nv_bfloat16*& dl, int& off) {
    if (id < W8)          { src = wq; dh = g_wqh; dl = g_wql; off = id; }
    else if (id < 2 * W8) { src = wk; dh = g_wkh; dl = g_wkl; off = id - W8; }
    else if (id < 3 * W8) { src = wv; dh = g_wvh; dl = g_wvl; off = id - 2 * W8; }
    else if (id < 4 * W8) { src = wo; dh = g_woh; dl = g_wol; off = id - 3 * W8; }
    else                  { src = x;  dh = g_xh;  dl = g_xl;  off = id - 4 * W8; }
}

__global__ __launch_bounds__(256) void conv_all(
    const float* __restrict__ wq, const float* __restrict__ wk,
    const float* __restrict__ wv, const float* __restrict__ wo,
    const float* __restrict__ x)
{
    const int total = 4 * W8 + X8;
    for (int id = blockIdx.x * 512 + threadIdx.x; id < total; id += gridDim.x * 512) {
        const int id2 = id + 256;
        const float *s0, *s1 = nullptr; __nv_bfloat16 *h0, *l0, *h1, *l1; int o0, o1;
        conv_route(id, wq, wk, wv, wo, x, s0, h0, l0, o0);
        float4 a0 = ((const float4*)s0)[(size_t)o0 * 2];
        float4 a1 = ((const float4*)s0)[(size_t)o0 * 2 + 1];
        float4 b0, b1;
        if (id2 < total) {
            conv_route(id2, wq, wk, wv, wo, x, s1, h1, l1, o1);
            b0 = ((const float4*)s1)[(size_t)o1 * 2];
            b1 = ((const float4*)s1)[(size_t)o1 * 2 + 1];
        }
        split8_store(a0, a1, h0, l0, o0);
        if (id2 < total) split8_store(b0, b1, h1, l1, o1);
    }
}

// =================================================================================
// bf16-split GEMM (3xBF16), BM=64 BN=64 BK=32, 256 thr, unchanged from R5.
// =================================================================================
template<int MODE>
__global__ __launch_bounds__(256) void gemm_bf16(
    const float* __restrict__ bi0, const float* __restrict__ bi1,
    const float* __restrict__ bi2, float* __restrict__ Out)
{
    __shared__ __align__(16) unsigned char smem[2 * 16384];

    const int tid  = threadIdx.x;
    const int lane = tid & 31;
    const int wid  = tid >> 5;
    const int gid  = lane >> 2;
    const int tig  = lane & 3;
    const int wm   = wid & 1;
    const int wn   = wid >> 1;
    const int bx = blockIdx.x;
    const int by = blockIdx.y;

    const __nv_bfloat16 *Ah, *Al, *Bh, *Bl;
    const float* bsel;
    float* dst = nullptr;
    int nrow0;
    if (MODE == 0) {
        const int type = by >> 5;
        Ah = g_xh; Al = g_xl;
        Bh = (type == 0) ? g_wqh : (type == 1) ? g_wkh : g_wvh;
        Bl = (type == 0) ? g_wql : (type == 1) ? g_wkl : g_wvl;
        bsel = (type == 0) ? bi0 : (type == 1) ? bi1 : bi2;
        dst  = (type == 0) ? g_q : (type == 1) ? g_kn : g_vn;
        nrow0 = (by & 31) * 64;
    } else {
        Ah = g_ah; Al = g_al; Bh = g_woh; Bl = g_wol;
        bsel = bi0;
        nrow0 = by * 64;
    }
    const int row0 = bx * 64;

    const unsigned sbase = (unsigned)__cvta_generic_to_shared(smem);

    const int sr = tid >> 2;
    const int sc = tid & 3;
    const unsigned sdst = sbase + (unsigned)(sr * 64 + (sc ^ ((sr >> 1) & 3)) * 16);
    const __nv_bfloat16* aSrc  = Ah + (size_t)(row0  + sr) * DM + sc * 8;
    const __nv_bfloat16* alSrc = Al + (size_t)(row0  + sr) * DM + sc * 8;
    const __nv_bfloat16* bSrc  = Bh + (size_t)(nrow0 + sr) * DM + sc * 8;
    const __nv_bfloat16* blSrc = Bl + (size_t)(nrow0 + sr) * DM + sc * 8;

    float acc[2][2][4];
#pragma unroll
    for (int i = 0; i < 2; i++)
#pragma unroll
        for (int j = 0; j < 2; j++)
#pragma unroll
            for (int q = 0; q < 4; q++) acc[i][j][q] = 0.f;

    const int a_l15 = lane & 15;
    const int ku_a  = lane >> 4;
    const int brow  = wn * 16 + ((lane & 7) | ((lane & 16) >> 1));
    const int ku_b  = (lane >> 3) & 1;

    {
        cp16(sdst,          aSrc);
        cp16(sdst + 4096u,  alSrc);
        cp16(sdst + 8192u,  bSrc);
        cp16(sdst + 12288u, blSrc);
        cp_commit();
    }

    for (int it = 0; it < DM / 32; ++it) {
        if (it < DM / 32 - 1) {
            const int ko = (it + 1) * 32;
            const unsigned d = sdst + (unsigned)(((it + 1) & 1) * 16384);
            cp16(d,          aSrc  + ko);
            cp16(d + 4096u,  alSrc + ko);
            cp16(d + 8192u,  bSrc  + ko);
            cp16(d + 12288u, blSrc + ko);
            cp_commit();
            cp_wait1();
        } else {
            cp_wait0();
        }
        __syncthreads();

        const unsigned sb = sbase + (unsigned)((it & 1) * 16384);
#pragma unroll
        for (int ks = 0; ks < 2; ks++) {
            unsigned ah[2][4], al_[2][4], bh[4], bl[4];
#pragma unroll
            for (int i = 0; i < 2; i++) {
                const int r  = wm * 32 + i * 16 + a_l15;
                const int pu = (ks * 2 + ku_a) ^ ((r >> 1) & 3);
                const unsigned ad = sb + (unsigned)(r * 64 + pu * 16);
                ldm_x4(ad,         ah[i][0],  ah[i][1],  ah[i][2],  ah[i][3]);
                ldm_x4(ad + 4096u, al_[i][0], al_[i][1], al_[i][2], al_[i][3]);
            }
            {
                const int pu = (ks * 2 + ku_b) ^ ((brow >> 1) & 3);
                const unsigned bd = sb + 8192u + (unsigned)(brow * 64 + pu * 16);
                ldm_x4(bd,         bh[0], bh[1], bh[2], bh[3]);
                ldm_x4(bd + 4096u, bl[0], bl[1], bl[2], bl[3]);
            }
#pragma unroll
            for (int i = 0; i < 2; i++)
#pragma unroll
                for (int j = 0; j < 2; j++) {
                    mma16(acc[i][j], ah[i],  bh[2 * j], bh[2 * j + 1]);
                    mma16(acc[i][j], ah[i],  bl[2 * j], bl[2 * j + 1]);
                    mma16(acc[i][j], al_[i], bh[2 * j], bh[2 * j + 1]);
                }
        }
        __syncthreads();
    }

#pragma unroll
    for (int i = 0; i < 2; i++) {
#pragma unroll
        for (int j = 0; j < 2; j++) {
#pragma unroll
            for (int q = 0; q < 4; q++) {
                const int m = row0 + wm * 32 + i * 16 + gid + ((q >= 2) ? 8 : 0);
                const int n = nrow0 + wn * 16 + j * 8 + 2 * tig + (q & 1);
                const float v = acc[i][j][q] + bsel[n];
                if (MODE == 0) {
                    const int h = n >> 6, d = n & 63;
                    const int bb = m >> 3, tt = m & 7;
                    dst[(((size_t)(bb * NH + h)) * NT + tt) * DH + d] = v;
                } else {
                    Out[(size_t)m * DM + n] = v;
                }
            }
        }
    }
}

// =================================================================================
// Attention per (b,h), f32x2 edition.  1024 blocks x 256 threads.
// smem: q[512] | p[8192] | kv[8704] | inv_sum[8]  = 69664 B (3 blocks/SM)
// Pass1: K staged s-pair-interleaved ([spair 32][dpair 32][par 2] x2floats,
//        row stride 132 floats), thread (t=warp, spair=lane), FFMA2 over d-pairs.
// Pass2: V staged plain 68-stride, thread (w=rowgroup, hb, dquad), FFMA2 d-pairs.
// Epilogue writes bf16 hi/lo split directly (no conv_attn kernel).
// =================================================================================
#define K_TILE_F 4224     // 32 pair-rows * 132 floats
#define V_ROW 68
#define V_TILE_F (64 * V_ROW)   // 4352
#define ATTN_SMEM_FLOATS (512 + 8192 + 2 * V_TILE_F + 8)

__device__ __forceinline__ void stage_k(unsigned kv_addr, int buf, int tile, int tid,
                                        const float* __restrict__ cache,
                                        const float* __restrict__ newer)
{
#pragma unroll
    for (int i = 0; i < 8; i++) {
        const int idx = tid + i * 256;        // 0..2047
        const int sl  = idx >> 5;             // row 0..63
        const int u   = idx & 31;             // d-pair unit
        const int s   = tile * 64 + sl;
        const float* src = (s < CT) ? (cache + (size_t)s * DH + u * 2)
                                    : (newer + (size_t)(s - CT) * DH + u * 2);
        const unsigned dst = kv_addr +
            (unsigned)(buf * (K_TILE_F * 4) + (sl >> 1) * 528 + u * 16 + (sl & 1) * 8);
        cp8(dst, src);
    }
    cp_commit();
}

__device__ __forceinline__ void stage_v(unsigned kv_addr, int buf, int tile, int tid,
                                        const float* __restrict__ cache,
                                        const float* __restrict__ newer)
{
#pragma unroll
    for (int i = 0; i < 4; i++) {
        const int idx = tid + i * 256;
        const int sl  = idx >> 4;
        const int c4  = idx & 15;
        const int s   = tile * 64 + sl;
        const float* src = (s < CT) ? (cache + (size_t)s * DH + c4 * 4)
                                    : (newer + (size_t)(s - CT) * DH + c4 * 4);
        const unsigned dst = kv_addr +
            (unsigned)((buf * V_TILE_F + sl * V_ROW + c4 * 4) * 4);
        cp8(dst, src);            // first 8B
        cp8(dst + 8u, (const char*)src + 8);  // second 8B
    }
    cp_commit();
}

__global__ __launch_bounds__(256) void attn_kernel(
    const float* __restrict__ cache_k,
    const float* __restrict__ cache_v)
{
    extern __shared__ float sm[];
    float* q_s     = sm;                    // 512
    float* p       = sm + 512;              // 8192
    float* kv      = p + 8192;              // 2*V_TILE_F (union K/V)
    float* inv_sum = kv + 2 * V_TILE_F;     // 8

    const int tid = threadIdx.x;
    const int w   = tid >> 5;
    const int l   = tid & 31;
    const int bh  = blockIdx.x;
    const int b   = bh >> 5;
    const int h   = bh & 31;

    const float* qsrc = g_q + (size_t)bh * (NT * DH);
    q_s[tid]       = qsrc[tid]       * 0.125f;
    q_s[tid + 256] = qsrc[tid + 256] * 0.125f;

    const float* ck = cache_k + (size_t)bh * CT * DH;
    const float* cv = cache_v + (size_t)bh * CT * DH;
    const float* kn = g_kn + (size_t)bh * (NT * DH);
    const float* vn = g_vn + (size_t)bh * (NT * DH);

    const unsigned kv_addr = (unsigned)__cvta_generic_to_shared(kv);

    // ---------------- Pass 1: scores = q @ K^T (FFMA2, s-pair interleaved) -------
    stage_k(kv_addr, 0, 0, tid, ck, kn);
    for (int c = 0; c < 16; c++) {
        if (c < 15) { stage_k(kv_addr, (c + 1) & 1, c + 1, tid, ck, kn); cp_wait1(); }
        else        { cp_wait0(); }
        __syncthreads();

        // thread: t = w, s-pair = l
        const ulonglong2* kb = (const ulonglong2*)(kv + (c & 1) * K_TILE_F) + l * 33;
        const ulonglong2* qb = (const ulonglong2*)(q_s + w * DH);

        unsigned long long a0 = 0ull, a1 = 0ull, b0 = 0ull, b1 = 0ull;
#pragma unroll
        for (int u = 0; u < 32; u += 2) {
            ulonglong2 k0 = kb[u];        // .x = s0 dpair, .y = s1 dpair
            ulonglong2 k1 = kb[u + 1];
            ulonglong2 qq = qb[u >> 1];   // .x = dpair u, .y = dpair u+1
            ffma2(a0, k0.x, qq.x);
            ffma2(a1, k0.y, qq.x);
            ffma2(b0, k1.x, qq.y);
            ffma2(b1, k1.y, qq.y);
        }
        float s0a, s0b, s1a, s1b, t0a, t0b, t1a, t1b;
        unpack2(a0, s0a, s0b); unpack2(b0, t0a, t0b);
        unpack2(a1, s1a, s1b); unpack2(b1, t1a, t1b);
        float2 r;
        r.x = (s0a + s0b) + (t0a + t0b);   // score for s = 2l
        r.y = (s1a + s1b) + (t1a + t1b);   // score for s = 2l+1
        *(float2*)(p + w * SEQ + c * 64 + 2 * l) = r;
        __syncthreads();
    }

    // prefetch first V tile
    stage_v(kv_addr, 0, 0, tid, cv, vn);

    // ---------------- softmax: warp w owns row t=w ----------------
    {
        float* pr = p + w * SEQ;
        float mx = -1e30f;
        for (int i = l; i < SEQ; i += 32) mx = fmaxf(mx, pr[i]);
#pragma unroll
        for (int o = 16; o; o >>= 1) mx = fmaxf(mx, __shfl_xor_sync(0xffffffffu, mx, o));
        float sum = 0.f;
        for (int i = l; i < SEQ; i += 32) {
            float e = __expf(pr[i] - mx);
            pr[i] = e;
            sum += e;
        }
#pragma unroll
        for (int o = 16; o; o >>= 1) sum += __shfl_xor_sync(0xffffffffu, sum, o);
        if (l == 0) inv_sum[w] = 1.0f / sum;
    }
    __syncthreads();

    // ---------------- Pass 2: out = p @ V (FFMA2 over d-pairs) ----------------
    const int hb  = l >> 4;       // row-half within warp's 8 rows
    const int q4i = l & 15;       // d-quad 0..15
    unsigned long long accA[8], accB[8];
#pragma unroll
    for (int t = 0; t < 8; t++) { accA[t] = 0ull; accB[t] = 0ull; }

    for (int c = 0; c < 16; c++) {
        if (c < 15) { stage_v(kv_addr, (c + 1) & 1, c + 1, tid, cv, vn); cp_wait1(); }
        else        { cp_wait0(); }
        __syncthreads();

        const float4* vb4 = (const float4*)(kv + (c & 1) * V_TILE_F);
        float4 pt[8];
#pragma unroll
        for (int t = 0; t < 8; t++)
            pt[t] = *(const float4*)(p + t * SEQ + c * 64 + w * 8 + hb * 4);

#pragma unroll
        for (int r = 0; r < 4; r++) {
            const int sl = w * 8 + hb * 4 + r;
            float4 vv = vb4[sl * 17 + q4i];
            unsigned long long vlo = pack2(vv.x, vv.y);
            unsigned long long vhi = pack2(vv.z, vv.w);
#pragma unroll
            for (int t = 0; t < 8; t++) {
                unsigned long long pp = pack_dup(((const float*)&pt[t])[r]);
                ffma2(accA[t], vlo, pp);
                ffma2(accB[t], vhi, pp);
            }
        }
        __syncthreads();
    }

    // ---------------- cross-partial reduce (reuse p: 16 sets x 512) ----------------
    float* red = p;
#pragma unroll
    for (int t = 0; t < 8; t++) {
        float x0, x1, x2, x3;
        unpack2(accA[t], x0, x1);
        unpack2(accB[t], x2, x3);
        float4 v4 = make_float4(x0, x1, x2, x3);
        *(float4*)(red + (w * 2 + hb) * 512 + t * 64 + q4i * 4) = v4;
    }
    __syncthreads();

    for (int i = tid; i < 512; i += 256) {
        float ssum = 0.f;
#pragma unroll
        for (int k2 = 0; k2 < 16; k2++) ssum += red[k2 * 512 + i];
        const int t = i >> 6, d = i & 63;
        const float val = ssum * inv_sum[t];
        __nv_bfloat16 hb2 = __float2bfloat16(val);
        __nv_bfloat16 lb2 = __float2bfloat16(val - __bfloat162float(hb2));
        const size_t o = ((size_t)(b * NT + t)) * DM + h * DH + d;
        g_ah[o] = hb2;
        g_al[o] = lb2;
    }
}

// =================================================================================
// launch
// =================================================================================
extern "C" void kernel_launch(void* const* d_in, const int* in_sizes, int n_in,
                              void* d_out, int out_size)
{
    const float* x        = (const float*)d_in[0];
    const float* cache_k  = (const float*)d_in[1];
    const float* cache_v  = (const float*)d_in[2];
    const float* Wq       = (const float*)d_in[3];
    const float* bq       = (const float*)d_in[4];
    const float* Wk       = (const float*)d_in[5];
    const float* bk       = (const float*)d_in[6];
    const float* Wv       = (const float*)d_in[7];
    const float* bv       = (const float*)d_in[8];
    const float* Wo       = (const float*)d_in[9];
    const float* bo       = (const float*)d_in[10];
    float*       out      = (float*)d_out;

    static const size_t attn_smem = (size_t)ATTN_SMEM_FLOATS * sizeof(float);
    cudaFuncSetAttribute(attn_kernel, cudaFuncAttributeMaxDynamicSharedMemorySize,
                         (int)attn_smem);

    conv_all<<<1184, 256>>>(Wq, Wk, Wv, Wo, x);

    dim3 gq(4, 96);
    gemm_bf16<0><<<gq, 256>>>(bq, bk, bv, nullptr);

    attn_kernel<<<NB * NH, 256, attn_smem>>>(cache_k, cache_v);

    dim3 go(4, 32);
    gemm_bf16<1><<<go, 256>>>(bo, nullptr, nullptr, out);
}

// round 7
// speedup vs baseline: 1.2074x; 1.2074x over previous
#include <cuda_runtime.h>
#include <cuda_bf16.h>

#define DM 2048
#define NB 32
#define NT 8
#define NH 32
#define DH 64
#define CT 1016
#define SEQ 1024
#define MROWS 256   // NB*NT

// ---------------- scratch (device globals; no allocation allowed) ----------------
__device__ float g_q   [NB*NH*NT*DH];   // [b][h][t][d]
__device__ float g_kn  [NB*NH*NT*DH];
__device__ float g_vn  [NB*NH*NT*DH];
__device__ float g_part0[MROWS*DM];     // oproj K-split partials
__device__ float g_part1[MROWS*DM];

// bf16 hi/lo split scratch
__device__ __align__(16) __nv_bfloat16 g_wqh[DM*DM], g_wql[DM*DM];
__device__ __align__(16) __nv_bfloat16 g_wkh[DM*DM], g_wkl[DM*DM];
__device__ __align__(16) __nv_bfloat16 g_wvh[DM*DM], g_wvl[DM*DM];
__device__ __align__(16) __nv_bfloat16 g_woh[DM*DM], g_wol[DM*DM];
__device__ __align__(16) __nv_bfloat16 g_xh[MROWS*DM], g_xl[MROWS*DM];
__device__ __align__(16) __nv_bfloat16 g_ah[MROWS*DM], g_al[MROWS*DM];  // attn out split

// ---------------- cp.async helpers ----------------
__device__ __forceinline__ void cp16(unsigned dst, const void* src) {
    asm volatile("cp.async.cg.shared.global [%0], [%1], 16;\n" :: "r"(dst), "l"(src));
}
__device__ __forceinline__ void cp_commit() {
    asm volatile("cp.async.commit_group;\n");
}
__device__ __forceinline__ void cp_wait1() {
    asm volatile("cp.async.wait_group 1;\n");
}
__device__ __forceinline__ void cp_wait0() {
    asm volatile("cp.async.wait_group 0;\n");
}

// ---------------- mma / ldmatrix helpers ----------------
__device__ __forceinline__ void ldm_x4(unsigned addr, unsigned& r0, unsigned& r1,
                                       unsigned& r2, unsigned& r3) {
    asm volatile("ldmatrix.sync.aligned.m8n8.x4.shared.b16 {%0,%1,%2,%3}, [%4];"
                 : "=r"(r0), "=r"(r1), "=r"(r2), "=r"(r3) : "r"(addr));
}
__device__ __forceinline__ void mma16(float* c, const unsigned* a, unsigned b0, unsigned b1) {
    asm volatile(
        "mma.sync.aligned.m16n8k16.row.col.f32.bf16.bf16.f32 "
        "{%0,%1,%2,%3}, {%4,%5,%6,%7}, {%8,%9}, {%0,%1,%2,%3};"
        : "+f"(c[0]), "+f"(c[1]), "+f"(c[2]), "+f"(c[3])
        : "r"(a[0]), "r"(a[1]), "r"(a[2]), "r"(a[3]), "r"(b0), "r"(b1));
}

// =================================================================================
// Prepass: split fp32 -> bf16 hi/lo for 4 weights + x, batch-2 for MLP
// =================================================================================
__device__ __forceinline__ void split8_store(const float4 f0, const float4 f1,
                                             __nv_bfloat16* dh, __nv_bfloat16* dl, size_t off) {
    float a[8] = {f0.x, f0.y, f0.z, f0.w, f1.x, f1.y, f1.z, f1.w};
    unsigned short h[8], l[8];
#pragma unroll
    for (int i = 0; i < 8; i++) {
        __nv_bfloat16 hb = __float2bfloat16(a[i]);
        __nv_bfloat16 lb = __float2bfloat16(a[i] - __bfloat162float(hb));
        h[i] = __bfloat16_as_ushort(hb);
        l[i] = __bfloat16_as_ushort(lb);
    }
    uint4 hs, ls;
    hs.x = (unsigned)h[0] | ((unsigned)h[1] << 16);
    hs.y = (unsigned)h[2] | ((unsigned)h[3] << 16);
    hs.z = (unsigned)h[4] | ((unsigned)h[5] << 16);
    hs.w = (unsigned)h[6] | ((unsigned)h[7] << 16);
    ls.x = (unsigned)l[0] | ((unsigned)l[1] << 16);
    ls.y = (unsigned)l[2] | ((unsigned)l[3] << 16);
    ls.z = (unsigned)l[4] | ((unsigned)l[5] << 16);
    ls.w = (unsigned)l[6] | ((unsigned)l[7] << 16);
    ((uint4*)dh)[off] = hs;
    ((uint4*)dl)[off] = ls;
}

#define W8 (DM * DM / 8)
#define X8 (MROWS * DM / 8)

__device__ __forceinline__ void conv_route(int id, const float* wq, const float* wk,
                                           const float* wv, const float* wo, const float* x,
                                           const float*& src, __nv_bfloat16*& dh,
                                           __nv_bfloat16*& dl, int& off) {
    if (id < W8)          { src = wq; dh = g_wqh; dl = g_wql; off = id; }
    else if (id < 2 * W8) { src = wk; dh = g_wkh; dl = g_wkl; off = id - W8; }
    else if (id < 3 * W8) { src = wv; dh = g_wvh; dl = g_wvl; off = id - 2 * W8; }
    else if (id < 4 * W8) { src = wo; dh = g_woh; dl = g_wol; off = id - 3 * W8; }
    else                  { src = x;  dh = g_xh;  dl = g_xl;  off = id - 4 * W8; }
}

__global__ __launch_bounds__(256) void conv_all(
    const float* __restrict__ wq, const float* __restrict__ wk,
    const float* __restrict__ wv, const float* __restrict__ wo,
    const float* __restrict__ x)
{
    const int total = 4 * W8 + X8;
    for (int id = blockIdx.x * 512 + threadIdx.x; id < total; id += gridDim.x * 512) {
        const int id2 = id + 256;
        const float *s0, *s1 = nullptr; __nv_bfloat16 *h0, *l0, *h1, *l1; int o0, o1;
        conv_route(id, wq, wk, wv, wo, x, s0, h0, l0, o0);
        float4 a0 = ((const float4*)s0)[(size_t)o0 * 2];
        float4 a1 = ((const float4*)s0)[(size_t)o0 * 2 + 1];
        float4 b0, b1;
        if (id2 < total) {
            conv_route(id2, wq, wk, wv, wo, x, s1, h1, l1, o1);
            b0 = ((const float4*)s1)[(size_t)o1 * 2];
            b1 = ((const float4*)s1)[(size_t)o1 * 2 + 1];
        }
        split8_store(a0, a1, h0, l0, o0);
        if (id2 < total) split8_store(b0, b1, h1, l1, o1);
    }
}

// =================================================================================
// bf16-split GEMM (3xBF16), BM=64 BN=64 BK=32, 256 thr.
// MODE 0: QKV, full K, scatter to g_q/g_kn/g_vn (+bias).
// MODE 1: O-proj, K split by blockIdx.z (z=0: k[0,1024), z=1: k[1024,2048)),
//         partials to g_part0/g_part1, NO bias (reduce kernel adds it).
// =================================================================================
template<int MODE>
__global__ __launch_bounds__(256) void gemm_bf16(
    const float* __restrict__ bi0, const float* __restrict__ bi1,
    const float* __restrict__ bi2)
{
    __shared__ __align__(16) unsigned char smem[2 * 16384];

    const int tid  = threadIdx.x;
    const int lane = tid & 31;
    const int wid  = tid >> 5;
    const int gid  = lane >> 2;
    const int tig  = lane & 3;
    const int wm   = wid & 1;
    const int wn   = wid >> 1;
    const int bx = blockIdx.x;
    const int by = blockIdx.y;
    const int bz = blockIdx.z;

    const __nv_bfloat16 *Ah, *Al, *Bh, *Bl;
    const float* bsel = nullptr;
    float* dst = nullptr;
    float* pOut = nullptr;
    int nrow0;
    int it0, it1;
    if (MODE == 0) {
        const int type = by >> 5;
        Ah = g_xh; Al = g_xl;
        Bh = (type == 0) ? g_wqh : (type == 1) ? g_wkh : g_wvh;
        Bl = (type == 0) ? g_wql : (type == 1) ? g_wkl : g_wvl;
        bsel = (type == 0) ? bi0 : (type == 1) ? bi1 : bi2;
        dst  = (type == 0) ? g_q : (type == 1) ? g_kn : g_vn;
        nrow0 = (by & 31) * 64;
        it0 = 0; it1 = DM / 32;
    } else {
        Ah = g_ah; Al = g_al; Bh = g_woh; Bl = g_wol;
        pOut = bz ? g_part1 : g_part0;
        nrow0 = by * 64;
        it0 = bz * (DM / 64); it1 = it0 + DM / 64;
    }
    const int row0 = bx * 64;

    const unsigned sbase = (unsigned)__cvta_generic_to_shared(smem);

    const int sr = tid >> 2;
    const int sc = tid & 3;
    const unsigned sdst = sbase + (unsigned)(sr * 64 + (sc ^ ((sr >> 1) & 3)) * 16);
    const __nv_bfloat16* aSrc  = Ah + (size_t)(row0  + sr) * DM + sc * 8;
    const __nv_bfloat16* alSrc = Al + (size_t)(row0  + sr) * DM + sc * 8;
    const __nv_bfloat16* bSrc  = Bh + (size_t)(nrow0 + sr) * DM + sc * 8;
    const __nv_bfloat16* blSrc = Bl + (size_t)(nrow0 + sr) * DM + sc * 8;

    float acc[2][2][4];
#pragma unroll
    for (int i = 0; i < 2; i++)
#pragma unroll
        for (int j = 0; j < 2; j++)
#pragma unroll
            for (int q = 0; q < 4; q++) acc[i][j][q] = 0.f;

    const int a_l15 = lane & 15;
    const int ku_a  = lane >> 4;
    const int brow  = wn * 16 + ((lane & 7) | ((lane & 16) >> 1));
    const int ku_b  = (lane >> 3) & 1;

    {
        const int ko = it0 * 32;
        cp16(sdst,          aSrc  + ko);
        cp16(sdst + 4096u,  alSrc + ko);
        cp16(sdst + 8192u,  bSrc  + ko);
        cp16(sdst + 12288u, blSrc + ko);
        cp_commit();
    }

    for (int it = it0; it < it1; ++it) {
        if (it < it1 - 1) {
            const int ko = (it + 1) * 32;
            const unsigned d = sdst + (unsigned)(((it - it0 + 1) & 1) * 16384);
            cp16(d,          aSrc  + ko);
            cp16(d + 4096u,  alSrc + ko);
            cp16(d + 8192u,  bSrc  + ko);
            cp16(d + 12288u, blSrc + ko);
            cp_commit();
            cp_wait1();
        } else {
            cp_wait0();
        }
        __syncthreads();

        const unsigned sb = sbase + (unsigned)(((it - it0) & 1) * 16384);
#pragma unroll
        for (int ks = 0; ks < 2; ks++) {
            unsigned ah[2][4], al_[2][4], bh[4], bl[4];
#pragma unroll
            for (int i = 0; i < 2; i++) {
                const int r  = wm * 32 + i * 16 + a_l15;
                const int pu = (ks * 2 + ku_a) ^ ((r >> 1) & 3);
                const unsigned ad = sb + (unsigned)(r * 64 + pu * 16);
                ldm_x4(ad,         ah[i][0],  ah[i][1],  ah[i][2],  ah[i][3]);
                ldm_x4(ad + 4096u, al_[i][0], al_[i][1], al_[i][2], al_[i][3]);
            }
            {
                const int pu = (ks * 2 + ku_b) ^ ((brow >> 1) & 3);
                const unsigned bd = sb + 8192u + (unsigned)(brow * 64 + pu * 16);
                ldm_x4(bd,         bh[0], bh[1], bh[2], bh[3]);
                ldm_x4(bd + 4096u, bl[0], bl[1], bl[2], bl[3]);
            }
#pragma unroll
            for (int i = 0; i < 2; i++)
#pragma unroll
                for (int j = 0; j < 2; j++) {
                    mma16(acc[i][j], ah[i],  bh[2 * j], bh[2 * j + 1]);
                    mma16(acc[i][j], ah[i],  bl[2 * j], bl[2 * j + 1]);
                    mma16(acc[i][j], al_[i], bh[2 * j], bh[2 * j + 1]);
                }
        }
        __syncthreads();
    }

#pragma unroll
    for (int i = 0; i < 2; i++) {
#pragma unroll
        for (int j = 0; j < 2; j++) {
#pragma unroll
            for (int q = 0; q < 4; q++) {
                const int m = row0 + wm * 32 + i * 16 + gid + ((q >= 2) ? 8 : 0);
                const int n = nrow0 + wn * 16 + j * 8 + 2 * tig + (q & 1);
                if (MODE == 0) {
                    const float v = acc[i][j][q] + bsel[n];
                    const int h = n >> 6, d = n & 63;
                    const int bb = m >> 3, tt = m & 7;
                    dst[(((size_t)(bb * NH + h)) * NT + tt) * DH + d] = v;
                } else {
                    pOut[(size_t)m * DM + n] = acc[i][j][q];
                }
            }
        }
    }
}

// oproj partial reduce + bias -> out
__global__ __launch_bounds__(256) void reduce_bias(
    const float* __restrict__ bo, float* __restrict__ out)
{
    const int i = blockIdx.x * 256 + threadIdx.x;   // float4 index, 131072 total
    float4 a = ((const float4*)g_part0)[i];
    float4 b = ((const float4*)g_part1)[i];
    const int n4 = (i & (DM / 4 - 1)) * 4;
    float4 bb = *(const float4*)(bo + n4);
    float4 r;
    r.x = a.x + b.x + bb.x;
    r.y = a.y + b.y + bb.y;
    r.z = a.z + b.z + bb.z;
    r.w = a.w + b.w + bb.w;
    ((float4*)out)[i] = r;
}

// =================================================================================
// Attention per (b,h). 1024 blocks x 256 threads. (R5 structure, bf16-split epi)
// =================================================================================
#define KV_ROW 68
#define KV_TILE (64 * KV_ROW)
#define ATTN_SMEM_FLOATS (512 + 8192 + 2 * KV_TILE + 8)

__device__ __forceinline__ void stage_tile(unsigned kv_smem_addr, int buf, int tile, int tid,
                                           const float* __restrict__ cache,
                                           const float* __restrict__ newer)
{
#pragma unroll
    for (int i = 0; i < 4; i++) {
        const int idx = tid + i * 256;
        const int sl  = idx >> 4;
        const int c4  = idx & 15;
        const int s   = tile * 64 + sl;
        const float* src = (s < CT) ? (cache + (size_t)s * DH + c4 * 4)
                                    : (newer + (size_t)(s - CT) * DH + c4 * 4);
        const unsigned dstoff = (unsigned)((buf * KV_TILE + sl * KV_ROW + c4 * 4) * 4);
        cp16(kv_smem_addr + dstoff, src);
    }
    cp_commit();
}

__global__ __launch_bounds__(256) void attn_kernel(
    const float* __restrict__ cache_k,
    const float* __restrict__ cache_v)
{
    extern __shared__ float sm[];
    float* q_s     = sm;
    float* p       = sm + 512;
    float* kv      = p + 8192;
    float* inv_sum = kv + 2 * KV_TILE;

    const int tid = threadIdx.x;
    const int w   = tid >> 5;
    const int l   = tid & 31;
    const int bh  = blockIdx.x;
    const int b   = bh >> 5;
    const int h   = bh & 31;

    const float* qsrc = g_q + (size_t)bh * (NT * DH);
    q_s[tid]       = qsrc[tid]       * 0.125f;
    q_s[tid + 256] = qsrc[tid + 256] * 0.125f;

    const float* ck = cache_k + (size_t)bh * CT * DH;
    const float* cv = cache_v + (size_t)bh * CT * DH;
    const float* kn = g_kn + (size_t)bh * (NT * DH);
    const float* vn = g_vn + (size_t)bh * (NT * DH);

    const unsigned kv_addr = (unsigned)__cvta_generic_to_shared(kv);

    // Pass 1: scores = q @ K^T
    stage_tile(kv_addr, 0, 0, tid, ck, kn);
    for (int c = 0; c < 16; c++) {
        if (c < 15) { stage_tile(kv_addr, (c + 1) & 1, c + 1, tid, ck, kn); cp_wait1(); }
        else        { cp_wait0(); }
        __syncthreads();

        const float* kb = kv + (c & 1) * KV_TILE;
        const int g  = tid >> 6;
        const int sl = tid & 63;
        const int t0 = g * 2, t1 = g * 2 + 1;
        float a0 = 0.f, a1 = 0.f;
        const float4* krow = (const float4*)(kb + sl * KV_ROW);
        const float4* q0   = (const float4*)(q_s + t0 * DH);
        const float4* q1   = (const float4*)(q_s + t1 * DH);
#pragma unroll
        for (int c4 = 0; c4 < 16; c4++) {
            float4 kk = krow[c4];
            float4 qa = q0[c4], qb = q1[c4];
            a0 += kk.x * qa.x + kk.y * qa.y + kk.z * qa.z + kk.w * qa.w;
            a1 += kk.x * qb.x + kk.y * qb.y + kk.z * qb.z + kk.w * qb.w;
        }
        const int s = c * 64 + sl;
        p[t0 * SEQ + s] = a0;
        p[t1 * SEQ + s] = a1;
        __syncthreads();
    }

    stage_tile(kv_addr, 0, 0, tid, cv, vn);

    // softmax
    {
        float* pr = p + w * SEQ;
        float mx = -1e30f;
        for (int i = l; i < SEQ; i += 32) mx = fmaxf(mx, pr[i]);
#pragma unroll
        for (int o = 16; o; o >>= 1) mx = fmaxf(mx, __shfl_xor_sync(0xffffffffu, mx, o));
        float sum = 0.f;
        for (int i = l; i < SEQ; i += 32) {
            float e = __expf(pr[i] - mx);
            pr[i] = e;
            sum += e;
        }
#pragma unroll
        for (int o = 16; o; o >>= 1) sum += __shfl_xor_sync(0xffffffffu, sum, o);
        if (l == 0) inv_sum[w] = 1.0f / sum;
    }
    __syncthreads();

    // Pass 2: out = p @ V
    float acc[8][2];
#pragma unroll
    for (int t = 0; t < 8; t++) { acc[t][0] = 0.f; acc[t][1] = 0.f; }

    for (int c = 0; c < 16; c++) {
        if (c < 15) { stage_tile(kv_addr, (c + 1) & 1, c + 1, tid, cv, vn); cp_wait1(); }
        else        { cp_wait0(); }
        __syncthreads();

        const float* vb = kv + (c & 1) * KV_TILE;
#pragma unroll
        for (int r = 0; r < 8; r++) {
            const int sl = w * 8 + r;
            const float v0 = vb[sl * KV_ROW + l];
            const float v1 = vb[sl * KV_ROW + 32 + l];
            const int s = c * 64 + sl;
#pragma unroll
            for (int t = 0; t < 8; t++) {
                const float pw = p[t * SEQ + s];
                acc[t][0] += pw * v0;
                acc[t][1] += pw * v1;
            }
        }
        __syncthreads();
    }

    float* red = p;
#pragma unroll
    for (int t = 0; t < 8; t++) {
        red[w * 512 + t * 64 + l]      = acc[t][0];
        red[w * 512 + t * 64 + 32 + l] = acc[t][1];
    }
    __syncthreads();
    for (int i = tid; i < 512; i += 256) {
        float ssum = 0.f;
#pragma unroll
        for (int ww = 0; ww < 8; ww++) ssum += red[ww * 512 + i];
        const int t = i >> 6, d = i & 63;
        const float val = ssum * inv_sum[t];
        __nv_bfloat16 hb2 = __float2bfloat16(val);
        __nv_bfloat16 lb2 = __float2bfloat16(val - __bfloat162float(hb2));
        const size_t o = ((size_t)(b * NT + t)) * DM + h * DH + d;
        g_ah[o] = hb2;
        g_al[o] = lb2;
    }
}

// =================================================================================
// launch
// =================================================================================
extern "C" void kernel_launch(void* const* d_in, const int* in_sizes, int n_in,
                              void* d_out, int out_size)
{
    const float* x        = (const float*)d_in[0];
    const float* cache_k  = (const float*)d_in[1];
    const float* cache_v  = (const float*)d_in[2];
    const float* Wq       = (const float*)d_in[3];
    const float* bq       = (const float*)d_in[4];
    const float* Wk       = (const float*)d_in[5];
    const float* bk       = (const float*)d_in[6];
    const float* Wv       = (const float*)d_in[7];
    const float* bv       = (const float*)d_in[8];
    const float* Wo       = (const float*)d_in[9];
    const float* bo       = (const float*)d_in[10];
    float*       out      = (float*)d_out;

    static const size_t attn_smem = (size_t)ATTN_SMEM_FLOATS * sizeof(float);
    cudaFuncSetAttribute(attn_kernel, cudaFuncAttributeMaxDynamicSharedMemorySize,
                         (int)attn_smem);

    conv_all<<<1184, 256>>>(Wq, Wk, Wv, Wo, x);

    dim3 gq(4, 96);
    gemm_bf16<0><<<gq, 256>>>(bq, bk, bv);

    attn_kernel<<<NB * NH, 256, attn_smem>>>(cache_k, cache_v);

    dim3 go(4, 32, 2);
    gemm_bf16<1><<<go, 256>>>(nullptr, nullptr, nullptr);

    reduce_bias<<<512, 256>>>(bo, out);
}